// round 6
// baseline (speedup 1.0000x reference)
#include <cuda_runtime.h>
#include <cuda_bf16.h>
#include <cstdint>

// Problem constants (fixed by the dataset)
#define N_FEAT   131072
#define DIM      128
#define K_CENT   1024
#define M_TILE   128           // features per CTA
#define N_CHUNK  64            // centers per SMEM chunk
#define N_CTAS   (N_FEAT / M_TILE)   // 1024
#define SMEM_BYTES ((M_TILE + N_CHUNK) * 256)   // 49152

// ---------------- device scratch (no allocation allowed) ----------------
__device__ __nv_bfloat16 g_cbf[K_CENT * DIM];  // normalized centers, bf16
__device__ float         g_cn1[K_CENT];         // ||C_k||
__device__ float         g_cn2[K_CENT];         // ||C_k||^2
__device__ float         g_partial[N_CTAS];     // per-CTA loss partial sums

// ---------------- helpers ----------------
__device__ __forceinline__ unsigned pack_bf16x2(float lo, float hi) {
    __nv_bfloat162 p = __floats2bfloat162_rn(lo, hi);
    return *reinterpret_cast<unsigned*>(&p);
}

__device__ __forceinline__ void ldm_x4(uint32_t& r0, uint32_t& r1, uint32_t& r2,
                                       uint32_t& r3, uint32_t addr) {
    asm volatile("ldmatrix.sync.aligned.m8n8.x4.shared.b16 {%0,%1,%2,%3}, [%4];\n"
                 : "=r"(r0), "=r"(r1), "=r"(r2), "=r"(r3)
                 : "r"(addr));
}

__device__ __forceinline__ void mma_bf16(float* c,
                                         uint32_t a0, uint32_t a1, uint32_t a2, uint32_t a3,
                                         uint32_t b0, uint32_t b1) {
    asm volatile("mma.sync.aligned.m16n8k16.row.col.f32.bf16.bf16.f32 "
                 "{%0,%1,%2,%3}, {%4,%5,%6,%7}, {%8,%9}, {%0,%1,%2,%3};\n"
                 : "+f"(c[0]), "+f"(c[1]), "+f"(c[2]), "+f"(c[3])
                 : "r"(a0), "r"(a1), "r"(a2), "r"(a3), "r"(b0), "r"(b1));
}

// ---------------- kernel 1: normalize centers ----------------
__global__ void prep_centers(const float* __restrict__ C) {
    int k = blockIdx.x;
    int t = threadIdx.x;          // 0..127 (one element per thread)
    float v = C[(size_t)k * DIM + t];
    float ss = v * v;
    #pragma unroll
    for (int off = 16; off; off >>= 1) ss += __shfl_xor_sync(0xffffffffu, ss, off);
    __shared__ float s4[4];
    if ((t & 31) == 0) s4[t >> 5] = ss;
    __syncthreads();
    float tot  = s4[0] + s4[1] + s4[2] + s4[3];
    float norm = sqrtf(tot);
    float inv  = 1.0f / fmaxf(norm, 1e-12f);
    g_cbf[(size_t)k * DIM + t] = __float2bfloat16(v * inv);
    if (t == 0) { g_cn1[k] = norm; g_cn2[k] = tot; }
}

// ---------------- kernel 2: fused GEMM + argmax + loss ----------------
// SMEM layout (XOR-swizzled, 256 B per logical row of 128 bf16):
//   A (features) : M_TILE rows  = 32768 B  at offset 0
//   B (centers)  : N_CHUNK rows = 16384 B  at offset 32768
// swizzle: 16B chunk c (0..15) of row r stored at chunk (c ^ (r & 7))
// NOTE: no static __shared__ here — total SMEM must stay at exactly 49152 B.
// The epilogue warp-partial array reuses the (dead) A-tile region.
__global__ void __launch_bounds__(256)
cluster_main(const float* __restrict__ F) {
    extern __shared__ unsigned char smem_raw[];
    unsigned char* Ash = smem_raw;
    unsigned char* Bsh = smem_raw + M_TILE * 256;

    const int t    = threadIdx.x;
    const int lane = t & 31;
    const int warp = t >> 5;               // 0..7, owns rows warp*16..+15
    const int m0   = blockIdx.x * M_TILE;

    // ---- load + normalize features into swizzled bf16 SMEM ----
    {
        int r = t >> 1;                    // 0..127 (2 threads per row)
        int h = t & 1;                     // half of the row (64 floats each)
        const float4* gp =
            reinterpret_cast<const float4*>(F + (size_t)(m0 + r) * DIM + h * 64);
        float ss = 0.f;
        #pragma unroll
        for (int i = 0; i < 16; i++) {
            float4 a = gp[i];
            ss += a.x * a.x + a.y * a.y + a.z * a.z + a.w * a.w;
        }
        ss += __shfl_xor_sync(0xffffffffu, ss, 1);   // partner lane = same row
        float inv = 1.0f / fmaxf(sqrtf(ss), 1e-12f);
        #pragma unroll
        for (int i = 0; i < 8; i++) {
            float4 a = gp[2 * i];
            float4 b = gp[2 * i + 1];
            uint4 val;
            val.x = pack_bf16x2(a.x * inv, a.y * inv);
            val.y = pack_bf16x2(a.z * inv, a.w * inv);
            val.z = pack_bf16x2(b.x * inv, b.y * inv);
            val.w = pack_bf16x2(b.z * inv, b.w * inv);
            int c  = h * 8 + i;            // 16B chunk index 0..15
            int cs = c ^ (r & 7);
            *reinterpret_cast<uint4*>(Ash + r * 256 + cs * 16) = val;
        }
    }

    // ---- precompute ldmatrix lane addressing ----
    const uint32_t a_base = (uint32_t)__cvta_generic_to_shared(Ash);
    const uint32_t b_base = (uint32_t)__cvta_generic_to_shared(Bsh);
    const int sub = lane >> 3, li = lane & 7;

    // A frag: matrices 0..3 = (m+0,k+0),(m+8,k+0),(m+0,k+8),(m+8,k+8)
    const int a_row      = warp * 16 + ((sub & 1) << 3) + li;
    const int a_cadd     = (sub >> 1);          // +1 chunk for k+8
    const int a_r7       = a_row & 7;
    const uint32_t a_rowaddr = a_base + a_row * 256;

    // B frag (x4 covers two n8 tiles): matrices = (n+0,k+0),(n+0,k+8),(n+8,k+0),(n+8,k+8)
    const int b_ck = (sub & 1);                 // +1 chunk for k+8
    uint32_t b_rowaddr[4];
    int      b_r7[4];
    #pragma unroll
    for (int j = 0; j < 4; j++) {
        int nr = 16 * j + ((sub >> 1) << 3) + li;
        b_rowaddr[j] = b_base + nr * 256;
        b_r7[j]      = nr & 7;
    }

    // B global-load addressing: thread loads 64 contiguous bytes of one center row
    const int bn = t >> 2;                      // center row within chunk 0..63
    const int bq = t & 3;                       // quarter of the row

    float best0v = -3.0e38f, best1v = -3.0e38f;
    int   best0i = 0,        best1i = 0;

    __syncthreads();                            // A ready for all warps

    for (int ch = 0; ch < K_CENT / N_CHUNK; ch++) {
        // stage 64 centers into swizzled SMEM
        {
            const uint4* gB = reinterpret_cast<const uint4*>(
                g_cbf + (size_t)(ch * N_CHUNK + bn) * DIM) + bq * 4;
            #pragma unroll
            for (int i = 0; i < 4; i++) {
                int c  = bq * 4 + i;
                int cs = c ^ (bn & 7);
                *reinterpret_cast<uint4*>(Bsh + bn * 256 + cs * 16) = gB[i];
            }
        }
        __syncthreads();

        float acc[8][4] = {};
        #pragma unroll
        for (int ks = 0; ks < 8; ks++) {        // k = ks*16
            uint32_t a0, a1, a2, a3;
            ldm_x4(a0, a1, a2, a3,
                   a_rowaddr + ((((ks << 1) + a_cadd) ^ a_r7) << 4));
            #pragma unroll
            for (int j = 0; j < 4; j++) {
                uint32_t b0, b1, b2, b3;
                ldm_x4(b0, b1, b2, b3,
                       b_rowaddr[j] + ((((ks << 1) + b_ck) ^ b_r7[j]) << 4));
                mma_bf16(acc[2 * j],     a0, a1, a2, a3, b0, b1);
                mma_bf16(acc[2 * j + 1], a0, a1, a2, a3, b2, b3);
            }
        }

        // running argmax for the two rows this thread owns (gid, gid+8)
        {
            int cbase0 = ch * N_CHUNK + (lane & 3) * 2;
            #pragma unroll
            for (int jj = 0; jj < 8; jj++) {
                int ci = cbase0 + jj * 8;
                if (acc[jj][0] > best0v) { best0v = acc[jj][0]; best0i = ci;     }
                if (acc[jj][1] > best0v) { best0v = acc[jj][1]; best0i = ci + 1; }
                if (acc[jj][2] > best1v) { best1v = acc[jj][2]; best1i = ci;     }
                if (acc[jj][3] > best1v) { best1v = acc[jj][3]; best1i = ci + 1; }
            }
        }
        __syncthreads();                        // before B is overwritten
    }

    // ---- reduce argmax across the 4 lanes of each row-quad ----
    #pragma unroll
    for (int off = 1; off <= 2; off <<= 1) {
        float ov0 = __shfl_xor_sync(0xffffffffu, best0v, off);
        int   oi0 = __shfl_xor_sync(0xffffffffu, best0i, off);
        if (ov0 > best0v || (ov0 == best0v && oi0 < best0i)) { best0v = ov0; best0i = oi0; }
        float ov1 = __shfl_xor_sync(0xffffffffu, best1v, off);
        int   oi1 = __shfl_xor_sync(0xffffffffu, best1i, off);
        if (ov1 > best1v || (ov1 == best1v && oi1 < best1i)) { best1v = ov1; best1i = oi1; }
    }

    // per-row loss: ||f_hat||^2 = 1;  f_hat . C = sim * ||C||
    float l = 0.0f;
    if ((lane & 3) == 0) {
        l  = 1.0f - 2.0f * best0v * g_cn1[best0i] + g_cn2[best0i];
        l += 1.0f - 2.0f * best1v * g_cn1[best1i] + g_cn2[best1i];
    }
    #pragma unroll
    for (int off = 16; off; off >>= 1) l += __shfl_xor_sync(0xffffffffu, l, off);

    // warp partials go into the (now dead) A-tile SMEM region
    float* red = reinterpret_cast<float*>(smem_raw);
    if (lane == 0) red[warp] = l;
    __syncthreads();
    if (t == 0) {
        float s = 0.f;
        #pragma unroll
        for (int w = 0; w < 8; w++) s += red[w];
        g_partial[blockIdx.x] = s;
    }
}

// ---------------- kernel 3: deterministic final reduce ----------------
__global__ void finalize_loss(float* __restrict__ out) {
    __shared__ float sh[256];
    int t = threadIdx.x;
    float s = g_partial[t] + g_partial[t + 256] + g_partial[t + 512] + g_partial[t + 768];
    sh[t] = s;
    __syncthreads();
    #pragma unroll
    for (int off = 128; off; off >>= 1) {
        if (t < off) sh[t] += sh[t + off];
        __syncthreads();
    }
    if (t == 0) out[0] = sh[0] / (float)N_FEAT;
}

// ---------------- launch ----------------
extern "C" void kernel_launch(void* const* d_in, const int* in_sizes, int n_in,
                              void* d_out, int out_size) {
    const float* features = (const float*)d_in[0];
    const float* centers  = (const float*)d_in[1];
    if (n_in >= 2 && in_sizes[0] < in_sizes[1]) {   // defensive: order by size
        const float* tmp = features; features = centers; centers = tmp;
    }
    // Belt + suspenders: raise the dynamic-SMEM cap (host-side attribute set,
    // not a stream operation — capture-safe and idempotent).
    cudaFuncSetAttribute(cluster_main,
                         cudaFuncAttributeMaxDynamicSharedMemorySize, 65536);
    prep_centers<<<K_CENT, DIM>>>(centers);
    cluster_main<<<N_CTAS, 256, SMEM_BYTES>>>(features);
    finalize_loss<<<1, 256>>>((float*)d_out);
}

// round 7
// speedup vs baseline: 1.3087x; 1.3087x over previous
#include <cuda_runtime.h>
#include <cuda_bf16.h>
#include <cstdint>

// Problem constants (fixed by the dataset)
#define N_FEAT   131072
#define DIM      128
#define K_CENT   1024
#define M_TILE   128                      // features per CTA
#define N_CHUNK  64                       // centers per SMEM chunk
#define N_CHUNKS (K_CENT / N_CHUNK)       // 16
#define N_CTAS   (N_FEAT / M_TILE)        // 1024
#define SMEM_BYTES 49152                  // 3 x 16KB B buffers (A staged in first 32KB)

// ---------------- device scratch (no allocation allowed) ----------------
__device__ __nv_bfloat16 g_cbf[K_CENT * DIM];  // normalized centers, bf16
__device__ float         g_cn1[K_CENT];         // ||C_k||
__device__ float         g_cn2[K_CENT];         // ||C_k||^2
__device__ float         g_partial[N_CTAS];     // per-CTA loss partial sums

// ---------------- helpers ----------------
__device__ __forceinline__ unsigned pack_bf16x2(float lo, float hi) {
    __nv_bfloat162 p = __floats2bfloat162_rn(lo, hi);
    return *reinterpret_cast<unsigned*>(&p);
}

__device__ __forceinline__ void ldm_x4(uint32_t& r0, uint32_t& r1, uint32_t& r2,
                                       uint32_t& r3, uint32_t addr) {
    asm volatile("ldmatrix.sync.aligned.m8n8.x4.shared.b16 {%0,%1,%2,%3}, [%4];\n"
                 : "=r"(r0), "=r"(r1), "=r"(r2), "=r"(r3)
                 : "r"(addr));
}

__device__ __forceinline__ void mma_bf16(float* c,
                                         uint32_t a0, uint32_t a1, uint32_t a2, uint32_t a3,
                                         uint32_t b0, uint32_t b1) {
    asm volatile("mma.sync.aligned.m16n8k16.row.col.f32.bf16.bf16.f32 "
                 "{%0,%1,%2,%3}, {%4,%5,%6,%7}, {%8,%9}, {%0,%1,%2,%3};\n"
                 : "+f"(c[0]), "+f"(c[1]), "+f"(c[2]), "+f"(c[3])
                 : "r"(a0), "r"(a1), "r"(a2), "r"(a3), "r"(b0), "r"(b1));
}

__device__ __forceinline__ void cp16(uint32_t dst_smem, const void* src) {
    asm volatile("cp.async.cg.shared.global [%0], [%1], 16;\n"
                 :: "r"(dst_smem), "l"(src));
}
#define CP_COMMIT() asm volatile("cp.async.commit_group;\n" ::: "memory")
#define CP_WAIT2()  asm volatile("cp.async.wait_group 2;\n" ::: "memory")

// ---------------- kernel 1: normalize centers ----------------
__global__ void prep_centers(const float* __restrict__ C) {
    int k = blockIdx.x;
    int t = threadIdx.x;          // 0..127
    float v = C[(size_t)k * DIM + t];
    float ss = v * v;
    #pragma unroll
    for (int off = 16; off; off >>= 1) ss += __shfl_xor_sync(0xffffffffu, ss, off);
    __shared__ float s4[4];
    if ((t & 31) == 0) s4[t >> 5] = ss;
    __syncthreads();
    float tot  = s4[0] + s4[1] + s4[2] + s4[3];
    float norm = sqrtf(tot);
    float inv  = 1.0f / fmaxf(norm, 1e-12f);
    g_cbf[(size_t)k * DIM + t] = __float2bfloat16(v * inv);
    if (t == 0) { g_cn1[k] = norm; g_cn2[k] = tot; }
}

// ---------------- kernel 2: fused GEMM + argmax + loss ----------------
// SMEM (48KB): initially A staging in [0,32768); after A fragments are
// registered, three B buffers live at offsets {32768, 0, 16384} (16KB each),
// filled by a 3-deep cp.async pipeline.
// Swizzle for all tiles: 16B chunk c of row r stored at chunk (c ^ (r & 7)),
// rows are 256B.
// Warp split: warp w computes M rows [32*(w&3), +32) x N cols [32*(w>>2), +32).
__global__ void __launch_bounds__(256)
cluster_main(const float* __restrict__ F) {
    extern __shared__ unsigned char smem_raw[];
    const uint32_t smem_u32 = (uint32_t)__cvta_generic_to_shared(smem_raw);

    const int t    = threadIdx.x;
    const int lane = t & 31;
    const int warp = t >> 5;
    const int mrow_base = (warp & 3) * 32;      // this warp's M rows
    const int nh        = warp >> 2;            // this warp's N half (0/1)
    const int m0   = blockIdx.x * M_TILE;

    // ---- B staging addressing (each thread: one center row quarter, 4x16B) ----
    const int bn  = t >> 2;                     // center row within chunk 0..63
    const int bq  = t & 3;                      // quarter of the 256B row
    uint32_t bdst[4];
    #pragma unroll
    for (int i = 0; i < 4; i++) {
        int c  = bq * 4 + i;
        int cs = c ^ (bn & 7);
        bdst[i] = bn * 256 + cs * 16;
    }
    const __nv_bfloat16* bsrc0 = g_cbf + (size_t)bn * DIM + bq * 32;

    const uint32_t bufoff_tab[3] = {32768u, 0u, 16384u};

    // ---- prefetch B chunk 0 into buffer 0 (offset 32768) ----
    #pragma unroll
    for (int i = 0; i < 4; i++) cp16(smem_u32 + 32768u + bdst[i], bsrc0 + i * 8);
    CP_COMMIT();

    // ---- load + normalize features into swizzled bf16 SMEM [0,32768) ----
    {
        int r = t >> 1;                    // 2 threads per feature row
        int h = t & 1;
        const float4* gp =
            reinterpret_cast<const float4*>(F + (size_t)(m0 + r) * DIM + h * 64);
        float ss = 0.f;
        #pragma unroll
        for (int i = 0; i < 16; i++) {
            float4 a = gp[i];
            ss += a.x * a.x + a.y * a.y + a.z * a.z + a.w * a.w;
        }
        ss += __shfl_xor_sync(0xffffffffu, ss, 1);   // partner lane = same row
        float inv = 1.0f / fmaxf(sqrtf(ss), 1e-12f);
        #pragma unroll
        for (int i = 0; i < 8; i++) {
            float4 a = gp[2 * i];
            float4 b = gp[2 * i + 1];
            uint4 val;
            val.x = pack_bf16x2(a.x * inv, a.y * inv);
            val.y = pack_bf16x2(a.z * inv, a.w * inv);
            val.z = pack_bf16x2(b.x * inv, b.y * inv);
            val.w = pack_bf16x2(b.z * inv, b.w * inv);
            int c  = h * 8 + i;
            int cs = c ^ (r & 7);
            *reinterpret_cast<uint4*>(smem_raw + r * 256 + cs * 16) = val;
        }
    }
    __syncthreads();

    // ---- register all A fragments (2 m-tiles x 8 k-steps x 4 regs) ----
    const int sub = lane >> 3, li = lane & 7;
    uint32_t af[2][8][4];
    #pragma unroll
    for (int mi = 0; mi < 2; mi++) {
        int a_row = mrow_base + 16 * mi + ((sub & 1) << 3) + li;
        uint32_t ra = smem_u32 + a_row * 256;
        int r7 = a_row & 7;
        int cadd = sub >> 1;
        #pragma unroll
        for (int ks = 0; ks < 8; ks++) {
            ldm_x4(af[mi][ks][0], af[mi][ks][1], af[mi][ks][2], af[mi][ks][3],
                   ra + ((((ks << 1) + cadd) ^ r7) << 4));
        }
    }
    __syncthreads();   // A region now dead -> becomes B buffers 1 and 2

    // ---- prefetch B chunks 1,2 into buffers at 0 / 16384 ----
    #pragma unroll
    for (int i = 0; i < 4; i++)
        cp16(smem_u32 + 0u + bdst[i], bsrc0 + (size_t)1 * N_CHUNK * DIM + i * 8);
    CP_COMMIT();
    #pragma unroll
    for (int i = 0; i < 4; i++)
        cp16(smem_u32 + 16384u + bdst[i], bsrc0 + (size_t)2 * N_CHUNK * DIM + i * 8);
    CP_COMMIT();

    // ---- B ldmatrix lane addressing (this warp's N half: 2 row-groups of 16) ----
    const int b_ck = sub & 1;                   // k-half select
    uint32_t b_off[2];
    int      b_r7[2];
    #pragma unroll
    for (int jj = 0; jj < 2; jj++) {
        int nr = 32 * nh + 16 * jj + ((sub >> 1) << 3) + li;
        b_off[jj] = nr * 256;
        b_r7[jj]  = nr & 7;
    }

    float bestv[2][2] = {{-3.0e38f, -3.0e38f}, {-3.0e38f, -3.0e38f}};
    int   besti[2][2] = {{0, 0}, {0, 0}};

    // ---- main loop over 16 center chunks, 3-stage cp.async pipeline ----
    for (int ch = 0; ch < N_CHUNKS; ch++) {
        CP_WAIT2();
        __syncthreads();
        const uint32_t bb = smem_u32 + bufoff_tab[ch % 3];

        float acc[2][4][4] = {};
        #pragma unroll
        for (int ks = 0; ks < 8; ks++) {
            #pragma unroll
            for (int jj = 0; jj < 2; jj++) {
                uint32_t b0, b1, b2, b3;
                ldm_x4(b0, b1, b2, b3,
                       bb + b_off[jj] + ((((ks << 1) + b_ck) ^ b_r7[jj]) << 4));
                mma_bf16(acc[0][2 * jj],     af[0][ks][0], af[0][ks][1], af[0][ks][2], af[0][ks][3], b0, b1);
                mma_bf16(acc[0][2 * jj + 1], af[0][ks][0], af[0][ks][1], af[0][ks][2], af[0][ks][3], b2, b3);
                mma_bf16(acc[1][2 * jj],     af[1][ks][0], af[1][ks][1], af[1][ks][2], af[1][ks][3], b0, b1);
                mma_bf16(acc[1][2 * jj + 1], af[1][ks][0], af[1][ks][1], af[1][ks][2], af[1][ks][3], b2, b3);
            }
        }

        // running argmax; rows: mrow_base+16*mi+(lane>>2)+8*h, cols increase with nt
        {
            int cb = ch * N_CHUNK + 32 * nh + (lane & 3) * 2;
            #pragma unroll
            for (int mi = 0; mi < 2; mi++) {
                #pragma unroll
                for (int nt = 0; nt < 4; nt++) {
                    int ci = cb + 8 * nt;
                    float* a4 = acc[mi][nt];
                    if (a4[0] > bestv[mi][0]) { bestv[mi][0] = a4[0]; besti[mi][0] = ci;     }
                    if (a4[1] > bestv[mi][0]) { bestv[mi][0] = a4[1]; besti[mi][0] = ci + 1; }
                    if (a4[2] > bestv[mi][1]) { bestv[mi][1] = a4[2]; besti[mi][1] = ci;     }
                    if (a4[3] > bestv[mi][1]) { bestv[mi][1] = a4[3]; besti[mi][1] = ci + 1; }
                }
            }
        }
        __syncthreads();   // all warps done reading this buffer

        // prefetch chunk ch+3 into the buffer just freed (always commit a group
        // so the wait_group<2> accounting at loop top stays uniform)
        if (ch + 3 < N_CHUNKS) {
            const __nv_bfloat16* s = bsrc0 + (size_t)(ch + 3) * N_CHUNK * DIM;
            uint32_t dstbase = smem_u32 + bufoff_tab[ch % 3];
            #pragma unroll
            for (int i = 0; i < 4; i++) cp16(dstbase + bdst[i], s + i * 8);
        }
        CP_COMMIT();
    }

    // ---- quad reduce argmax across the 4 lanes sharing each row ----
    #pragma unroll
    for (int off = 1; off <= 2; off <<= 1) {
        #pragma unroll
        for (int mi = 0; mi < 2; mi++) {
            #pragma unroll
            for (int h = 0; h < 2; h++) {
                float ov = __shfl_xor_sync(0xffffffffu, bestv[mi][h], off);
                int   oi = __shfl_xor_sync(0xffffffffu, besti[mi][h], off);
                if (ov > bestv[mi][h] || (ov == bestv[mi][h] && oi < besti[mi][h])) {
                    bestv[mi][h] = ov; besti[mi][h] = oi;
                }
            }
        }
    }

    // ---- combine the two N-half warps per row via SMEM, compute loss ----
    float* bv = reinterpret_cast<float*>(smem_raw);           // [2][128]
    int*   bi = reinterpret_cast<int*>(smem_raw + 1024);      // [2][128]
    if ((lane & 3) == 0) {
        int r0 = mrow_base + (lane >> 2);
        #pragma unroll
        for (int mi = 0; mi < 2; mi++) {
            #pragma unroll
            for (int h = 0; h < 2; h++) {
                int row = r0 + 16 * mi + 8 * h;
                bv[nh * 128 + row] = bestv[mi][h];
                bi[nh * 128 + row] = besti[mi][h];
            }
        }
    }
    __syncthreads();

    float* lr = reinterpret_cast<float*>(smem_raw + 2048);    // [128]
    if (t < 128) {
        float v0 = bv[t], v1 = bv[128 + t];
        int   i0 = bi[t], i1 = bi[128 + t];
        float v; int i;
        if (v0 > v1 || (v0 == v1 && i0 < i1)) { v = v0; i = i0; } else { v = v1; i = i1; }
        // loss row = ||f_hat||^2 - 2 f_hat.C + ||C||^2 ;  f_hat.C = sim * ||C||
        lr[t] = 1.0f - 2.0f * v * g_cn1[i] + g_cn2[i];
    }
    __syncthreads();
    #pragma unroll
    for (int off = 64; off; off >>= 1) {
        if (t < off) lr[t] += lr[t + off];
        __syncthreads();
    }
    if (t == 0) g_partial[blockIdx.x] = lr[0];
}

// ---------------- kernel 3: deterministic final reduce ----------------
__global__ void finalize_loss(float* __restrict__ out) {
    __shared__ float sh[256];
    int t = threadIdx.x;
    float s = g_partial[t] + g_partial[t + 256] + g_partial[t + 512] + g_partial[t + 768];
    sh[t] = s;
    __syncthreads();
    #pragma unroll
    for (int off = 128; off; off >>= 1) {
        if (t < off) sh[t] += sh[t + off];
        __syncthreads();
    }
    if (t == 0) out[0] = sh[0] / (float)N_FEAT;
}

// ---------------- launch ----------------
extern "C" void kernel_launch(void* const* d_in, const int* in_sizes, int n_in,
                              void* d_out, int out_size) {
    const float* features = (const float*)d_in[0];
    const float* centers  = (const float*)d_in[1];
    if (n_in >= 2 && in_sizes[0] < in_sizes[1]) {   // defensive: order by size
        const float* tmp = features; features = centers; centers = tmp;
    }
    cudaFuncSetAttribute(cluster_main,
                         cudaFuncAttributeMaxDynamicSharedMemorySize, 65536);
    prep_centers<<<K_CENT, DIM>>>(centers);
    cluster_main<<<N_CTAS, 256, SMEM_BYTES>>>(features);
    finalize_loss<<<1, 256>>>((float*)d_out);
}